// round 6
// baseline (speedup 1.0000x reference)
#include <cuda_runtime.h>
#include <math.h>
#include <stdint.h>

#define TTOK   2048
#define HDIM   768
#define NEXP   8
#define IDIM   768
#define MAXP   (TTOK*2)
#define ALPHA  1.702f
#define LIMIT  7.0f
#define BK     32
#define NCH    (HDIM / BK)   // 24

// -------- scratch --------
__device__ int   g_cnt[NEXP];
__device__ int   g_list[NEXP * MAXP];
__device__ float g_w[TTOK * 2];
__device__ float g_act[(size_t)TTOK * 2 * IDIM];   // stored tf32-rounded

// ------------------------- helpers -------------------------
__device__ __forceinline__ uint32_t tf32u(float x) {
    uint32_t u;
    asm("cvt.rna.tf32.f32 %0, %1;" : "=r"(u) : "f"(x));
    return u;
}
__device__ __forceinline__ float to_tf32f(float x) { return __uint_as_float(tf32u(x)); }
__device__ __forceinline__ void mma8(float* d, const uint32_t* a, const uint32_t* b) {
    asm volatile(
        "mma.sync.aligned.m16n8k8.row.col.f32.tf32.tf32.f32 "
        "{%0,%1,%2,%3}, {%4,%5,%6,%7}, {%8,%9}, {%0,%1,%2,%3};"
        : "+f"(d[0]), "+f"(d[1]), "+f"(d[2]), "+f"(d[3])
        : "r"(a[0]), "r"(a[1]), "r"(a[2]), "r"(a[3]), "r"(b[0]), "r"(b[1]));
}
__device__ __forceinline__ uint32_t smem_u32(const void* p) {
    uint32_t a;
    asm("{ .reg .u64 t; cvta.to.shared.u64 t, %1; cvt.u32.u64 %0, t; }"
        : "=r"(a) : "l"(p));
    return a;
}
__device__ __forceinline__ void cp16(uint32_t dst, const void* src, int sz) {
    asm volatile("cp.async.cg.shared.global [%0], [%1], 16, %2;"
                 :: "r"(dst), "l"(src), "r"(sz));
}
#define CP_COMMIT() asm volatile("cp.async.commit_group;" ::: "memory")
#define CP_WAIT(n)  asm volatile("cp.async.wait_group %0;" :: "n"(n) : "memory")

// A tile: 128 x 32 fp32, row stride 36 (bank-distinct)
// B tile:  32 x 64 fp32, row stride 72 (bank-distinct)
#define A_STRIDE 36
#define B_STRIDE 72
#define A_BYTES  (128 * A_STRIDE * 4)    // 18432
#define B_BYTES  (BK * B_STRIDE * 4)     // 9216

// ------------------------------ init ------------------------------
__global__ __launch_bounds__(256) void init_kernel(float* __restrict__ out)
{
    int idx = blockIdx.x * 256 + threadIdx.x;
    if (idx < NEXP) g_cnt[idx] = 0;
    if (idx < TTOK * HDIM / 4)
        ((float4*)out)[idx] = make_float4(0.f, 0.f, 0.f, 0.f);
}

// ------------------------------ router ------------------------------
__global__ __launch_bounds__(256) void router_kernel(
    const float* __restrict__ x, const float* __restrict__ Wr,
    const float* __restrict__ br)
{
    int warp = threadIdx.x >> 5;
    int lane = threadIdx.x & 31;
    int t = blockIdx.x * 8 + warp;
    if (t >= TTOK) return;

    const float4* xr = (const float4*)(x + (size_t)t * HDIM);
    float acc[NEXP];
#pragma unroll
    for (int e = 0; e < NEXP; e++) acc[e] = 0.f;

    for (int h4 = lane; h4 < HDIM / 4; h4 += 32) {
        float4 xv = xr[h4];
        const float* w = Wr + h4 * 4 * NEXP;
#pragma unroll
        for (int e = 0; e < NEXP; e++) {
            float s = fmaf(xv.x, w[e], 0.f);
            s = fmaf(xv.y, w[e + 8], s);
            s = fmaf(xv.z, w[e + 16], s);
            s = fmaf(xv.w, w[e + 24], s);
            acc[e] += s;
        }
    }
#pragma unroll
    for (int e = 0; e < NEXP; e++) {
#pragma unroll
        for (int o = 16; o > 0; o >>= 1)
            acc[e] += __shfl_xor_sync(0xffffffffu, acc[e], o);
    }
    if (lane == 0) {
#pragma unroll
        for (int e = 0; e < NEXP; e++) acc[e] += br[e];

        int i0 = 0; float v0 = acc[0];
#pragma unroll
        for (int e = 1; e < NEXP; e++)
            if (acc[e] > v0) { v0 = acc[e]; i0 = e; }
        int i1 = -1; float v1 = -INFINITY;
#pragma unroll
        for (int e = 0; e < NEXP; e++)
            if (e != i0 && acc[e] > v1) { v1 = acc[e]; i1 = e; }

        float s1 = expf(v1 - v0);
        float d  = 1.f + s1;
        g_w[t * 2 + 0] = 1.f / d;
        g_w[t * 2 + 1] = s1 / d;

        int p0 = atomicAdd(&g_cnt[i0], 1);
        g_list[i0 * MAXP + p0] = t * 2;
        int p1 = atomicAdd(&g_cnt[i1], 1);
        g_list[i1 * MAXP + p1] = t * 2 + 1;
    }
}

// =============== stage 1: tf32 mma gate/up GEMM + SwiGLU ===============
// 128 slots x 64 cols per plane, K in 24 chunks of 32, 3-stage cp.async.
#define GU_STAGE (A_BYTES + 2 * B_BYTES)   // 36864

__global__ __launch_bounds__(256, 2) void gu_mma(
    const float* __restrict__ x, const float* __restrict__ Wgu,
    const float* __restrict__ bgu)
{
    int e   = blockIdx.z;
    int cnt = g_cnt[e];
    int m0  = blockIdx.y * 128;
    if (m0 >= cnt) return;
    int n0  = blockIdx.x * 64;

    extern __shared__ __align__(16) char dsm[];
    __shared__ int sSlot[128];

    int tid  = threadIdx.x;
    int wid  = tid >> 5, lane = tid & 31;
    int wM   = wid >> 1, wN = wid & 1;
    int gID  = lane >> 2, tg = lane & 3;

    for (int m = tid; m < 128; m += 256) {
        int idx = m0 + m;
        sSlot[m] = (idx < cnt) ? g_list[e * MAXP + idx] : -1;
    }
    __syncthreads();

    const float* Wg = Wgu + (size_t)e * HDIM * (2 * IDIM);
    uint32_t smb = smem_u32(dsm);

    const float* aSrc[4]; int aSz[4]; uint32_t aDst[4];
#pragma unroll
    for (int i = 0; i < 4; i++) {
        int idx = tid + i * 256;
        int m = idx >> 3, kq = idx & 7;
        int slot = sSlot[m];
        aSrc[i] = (slot >= 0) ? x + (size_t)(slot >> 1) * HDIM + kq * 4 : x;
        aSz[i]  = (slot >= 0) ? 16 : 0;
        aDst[i] = (uint32_t)(m * A_STRIDE + kq * 4) * 4u;
    }
    const float* bSrc[2]; uint32_t bDst[2];
#pragma unroll
    for (int i = 0; i < 2; i++) {
        int idx = tid + i * 256;
        int k = idx >> 4, n4 = idx & 15;
        bSrc[i] = Wg + (size_t)k * (2 * IDIM) + n0 + n4 * 4;
        bDst[i] = (uint32_t)(k * B_STRIDE + n4 * 4) * 4u;
    }

    float accG[2][4][4], accU[2][4][4];
#pragma unroll
    for (int mt = 0; mt < 2; mt++)
#pragma unroll
        for (int nt = 0; nt < 4; nt++)
#pragma unroll
            for (int q = 0; q < 4; q++) { accG[mt][nt][q] = 0.f; accU[mt][nt][q] = 0.f; }

#define GU_ISSUE(c) do {                                                       \
    uint32_t st = smb + (uint32_t)((c) % 3) * GU_STAGE;                        \
    int k0 = (c) * BK;                                                         \
    _Pragma("unroll")                                                          \
    for (int i = 0; i < 4; i++) cp16(st + aDst[i], aSrc[i] + k0, aSz[i]);      \
    _Pragma("unroll")                                                          \
    for (int i = 0; i < 2; i++) {                                              \
        const float* bp = bSrc[i] + (size_t)k0 * (2 * IDIM);                   \
        cp16(st + A_BYTES + bDst[i],           bp,        16);                 \
        cp16(st + A_BYTES + B_BYTES + bDst[i], bp + IDIM, 16);                 \
    } } while (0)

    GU_ISSUE(0); CP_COMMIT();
    GU_ISSUE(1); CP_COMMIT();

    for (int c = 0; c < NCH; c++) {
        CP_WAIT(1);
        __syncthreads();
        if (c + 2 < NCH) GU_ISSUE(c + 2);
        CP_COMMIT();

        const float* fA  = (const float*)(dsm + (c % 3) * GU_STAGE);
        const float* fBg = (const float*)(dsm + (c % 3) * GU_STAGE + A_BYTES);
        const float* fBu = (const float*)(dsm + (c % 3) * GU_STAGE + A_BYTES + B_BYTES);

#pragma unroll
        for (int k8 = 0; k8 < 4; k8++) {
            int k = k8 * 8;
            uint32_t a[2][4];
#pragma unroll
            for (int mt = 0; mt < 2; mt++) {
                int r0 = wM * 32 + mt * 16 + gID;
                a[mt][0] = tf32u(fA[r0 * A_STRIDE + k + tg]);
                a[mt][1] = tf32u(fA[(r0 + 8) * A_STRIDE + k + tg]);
                a[mt][2] = tf32u(fA[r0 * A_STRIDE + k + tg + 4]);
                a[mt][3] = tf32u(fA[(r0 + 8) * A_STRIDE + k + tg + 4]);
            }
#pragma unroll
            for (int nt = 0; nt < 4; nt++) {
                int col = wN * 32 + nt * 8 + gID;
                uint32_t bg[2], bu[2];
                bg[0] = tf32u(fBg[(k + tg) * B_STRIDE + col]);
                bg[1] = tf32u(fBg[(k + tg + 4) * B_STRIDE + col]);
                bu[0] = tf32u(fBu[(k + tg) * B_STRIDE + col]);
                bu[1] = tf32u(fBu[(k + tg + 4) * B_STRIDE + col]);
#pragma unroll
                for (int mt = 0; mt < 2; mt++) {
                    mma8(accG[mt][nt], a[mt], bg);
                    mma8(accU[mt][nt], a[mt], bu);
                }
            }
        }
    }

    // ---- epilogue: bias + clamp + SwiGLU, tf32-rounded store to g_act ----
    const float* bge = bgu + (size_t)e * (2 * IDIM);
#pragma unroll
    for (int mt = 0; mt < 2; mt++) {
#pragma unroll
        for (int half = 0; half < 2; half++) {
            int row = wM * 32 + mt * 16 + half * 8 + gID;
            int slot = sSlot[row];
            if (slot < 0) continue;
            float* outp = g_act + (size_t)slot * IDIM;
#pragma unroll
            for (int nt = 0; nt < 4; nt++) {
                int col = n0 + wN * 32 + nt * 8 + 2 * tg;
                float g0 = accG[mt][nt][half * 2 + 0] + bge[col];
                float g1 = accG[mt][nt][half * 2 + 1] + bge[col + 1];
                float u0 = accU[mt][nt][half * 2 + 0] + bge[IDIM + col];
                float u1 = accU[mt][nt][half * 2 + 1] + bge[IDIM + col + 1];
                g0 = fminf(g0, LIMIT); g1 = fminf(g1, LIMIT);
                u0 = fmaxf(fminf(u0, LIMIT), -LIMIT);
                u1 = fmaxf(fminf(u1, LIMIT), -LIMIT);
                float s0 = 1.f / (1.f + expf(-ALPHA * g0));
                float s1 = 1.f / (1.f + expf(-ALPHA * g1));
                float2 o = make_float2(to_tf32f((u0 + 1.f) * (g0 * s0)),
                                       to_tf32f((u1 + 1.f) * (g1 * s1)));
                *(float2*)(outp + col) = o;
            }
        }
    }
}

// ====== stage 2: tf32 mma down GEMM, K-split 2, weighted atomic combine ======
#define DN_STAGE (A_BYTES + B_BYTES)   // 27648
#define KSPLIT   2
#define NCH_DN   (NCH / KSPLIT)        // 12

__global__ __launch_bounds__(256, 2) void down_mma(
    const float* __restrict__ Wd, const float* __restrict__ bd,
    float* __restrict__ out)
{
    int e   = blockIdx.z >> 1;
    int ks  = blockIdx.z & 1;
    int cnt = g_cnt[e];
    int m0  = blockIdx.y * 128;
    if (m0 >= cnt) return;
    int n0  = blockIdx.x * 64;
    int kbase = ks * (HDIM / KSPLIT);   // element offset in K

    extern __shared__ __align__(16) char dsm[];
    __shared__ int sSlot[128];

    int tid  = threadIdx.x;
    int wid  = tid >> 5, lane = tid & 31;
    int wM   = wid >> 1, wN = wid & 1;
    int gID  = lane >> 2, tg = lane & 3;

    for (int m = tid; m < 128; m += 256) {
        int idx = m0 + m;
        sSlot[m] = (idx < cnt) ? g_list[e * MAXP + idx] : -1;
    }
    __syncthreads();

    const float* We = Wd + (size_t)e * IDIM * HDIM;
    uint32_t smb = smem_u32(dsm);

    const float* aSrc[4]; int aSz[4]; uint32_t aDst[4];
#pragma unroll
    for (int i = 0; i < 4; i++) {
        int idx = tid + i * 256;
        int m = idx >> 3, kq = idx & 7;
        int slot = sSlot[m];
        aSrc[i] = (slot >= 0) ? g_act + (size_t)slot * IDIM + kbase + kq * 4 : g_act;
        aSz[i]  = (slot >= 0) ? 16 : 0;
        aDst[i] = (uint32_t)(m * A_STRIDE + kq * 4) * 4u;
    }
    const float* bSrc[2]; uint32_t bDst[2];
#pragma unroll
    for (int i = 0; i < 2; i++) {
        int idx = tid + i * 256;
        int k = idx >> 4, n4 = idx & 15;
        bSrc[i] = We + (size_t)(kbase + k) * HDIM + n0 + n4 * 4;
        bDst[i] = (uint32_t)(k * B_STRIDE + n4 * 4) * 4u;
    }

    float acc[2][4][4];
#pragma unroll
    for (int mt = 0; mt < 2; mt++)
#pragma unroll
        for (int nt = 0; nt < 4; nt++)
#pragma unroll
            for (int q = 0; q < 4; q++) acc[mt][nt][q] = 0.f;

#define DN_ISSUE(c) do {                                                       \
    uint32_t st = smb + (uint32_t)((c) % 3) * DN_STAGE;                        \
    int k0 = (c) * BK;                                                         \
    _Pragma("unroll")                                                          \
    for (int i = 0; i < 4; i++) cp16(st + aDst[i], aSrc[i] + k0, aSz[i]);      \
    _Pragma("unroll")                                                          \
    for (int i = 0; i < 2; i++)                                                \
        cp16(st + A_BYTES + bDst[i], bSrc[i] + (size_t)k0 * HDIM, 16);         \
    } while (0)

    DN_ISSUE(0); CP_COMMIT();
    DN_ISSUE(1); CP_COMMIT();

    for (int c = 0; c < NCH_DN; c++) {
        CP_WAIT(1);
        __syncthreads();
        if (c + 2 < NCH_DN) DN_ISSUE(c + 2);
        CP_COMMIT();

        const float* fA = (const float*)(dsm + (c % 3) * DN_STAGE);
        const float* fB = (const float*)(dsm + (c % 3) * DN_STAGE + A_BYTES);

#pragma unroll
        for (int k8 = 0; k8 < 4; k8++) {
            int k = k8 * 8;
            uint32_t a[2][4];
#pragma unroll
            for (int mt = 0; mt < 2; mt++) {
                int r0 = wM * 32 + mt * 16 + gID;
                a[mt][0] = __float_as_uint(fA[r0 * A_STRIDE + k + tg]);
                a[mt][1] = __float_as_uint(fA[(r0 + 8) * A_STRIDE + k + tg]);
                a[mt][2] = __float_as_uint(fA[r0 * A_STRIDE + k + tg + 4]);
                a[mt][3] = __float_as_uint(fA[(r0 + 8) * A_STRIDE + k + tg + 4]);
            }
#pragma unroll
            for (int nt = 0; nt < 4; nt++) {
                int col = wN * 32 + nt * 8 + gID;
                uint32_t b[2];
                b[0] = tf32u(fB[(k + tg) * B_STRIDE + col]);
                b[1] = tf32u(fB[(k + tg + 4) * B_STRIDE + col]);
#pragma unroll
                for (int mt = 0; mt < 2; mt++)
                    mma8(acc[mt][nt], a[mt], b);
            }
        }
    }

    // ---- epilogue: weighted atomic accumulate (bias only from slice 0) ----
    const float* bde = bd + (size_t)e * HDIM;
#pragma unroll
    for (int mt = 0; mt < 2; mt++) {
#pragma unroll
        for (int half = 0; half < 2; half++) {
            int row = wM * 32 + mt * 16 + half * 8 + gID;
            int slot = sSlot[row];
            if (slot < 0) continue;
            float w = g_w[slot];
            float* outp = out + (size_t)(slot >> 1) * HDIM;
#pragma unroll
            for (int nt = 0; nt < 4; nt++) {
                int col = n0 + wN * 32 + nt * 8 + 2 * tg;
                float b0 = ks ? 0.f : bde[col];
                float b1 = ks ? 0.f : bde[col + 1];
                atomicAdd(outp + col,     w * (acc[mt][nt][half * 2 + 0] + b0));
                atomicAdd(outp + col + 1, w * (acc[mt][nt][half * 2 + 1] + b1));
            }
        }
    }
}

// ------------------------------ launch ------------------------------
extern "C" void kernel_launch(void* const* d_in, const int* in_sizes, int n_in,
                              void* d_out, int out_size)
{
    const float* x   = (const float*)d_in[0];
    const float* Wr  = (const float*)d_in[1];
    const float* br  = (const float*)d_in[2];
    const float* Wgu = (const float*)d_in[3];
    const float* bgu = (const float*)d_in[4];
    const float* Wd  = (const float*)d_in[5];
    const float* bd  = (const float*)d_in[6];
    float* out = (float*)d_out;

    const int GU_SMEM = 3 * GU_STAGE;   // 110592
    const int DN_SMEM = 3 * DN_STAGE;   // 82944
    cudaFuncSetAttribute(gu_mma,   cudaFuncAttributeMaxDynamicSharedMemorySize, GU_SMEM);
    cudaFuncSetAttribute(down_mma, cudaFuncAttributeMaxDynamicSharedMemorySize, DN_SMEM);

    init_kernel<<<(TTOK * HDIM / 4 + 255) / 256, 256>>>(out);
    router_kernel<<<TTOK / 8, 256>>>(x, Wr, br);

    dim3 ggrid(IDIM / 64, MAXP / 128, NEXP);        // (12, 32, 8)
    gu_mma<<<ggrid, 256, GU_SMEM>>>(x, Wgu, bgu);

    dim3 dgrid(HDIM / 64, MAXP / 128, NEXP * 2);    // (12, 32, 16)
    down_mma<<<dgrid, 256, DN_SMEM>>>(Wd, bd, out);
}

// round 7
// speedup vs baseline: 1.0515x; 1.0515x over previous
#include <cuda_runtime.h>
#include <math.h>
#include <stdint.h>

#define TTOK   2048
#define HDIM   768
#define NEXP   8
#define IDIM   768
#define MAXP   (TTOK*2)
#define ALPHA  1.702f
#define LIMIT  7.0f
#define BK     32
#define NCH    (HDIM / BK)   // 24

// -------- scratch --------
__device__ int   g_cnt[NEXP];
__device__ int   g_list[NEXP * MAXP];
__device__ float g_w[TTOK * 2];
__device__ float g_act[(size_t)TTOK * 2 * IDIM];   // stored tf32-rounded

// ------------------------- helpers -------------------------
__device__ __forceinline__ uint32_t tf32u(float x) {
    uint32_t u;
    asm("cvt.rna.tf32.f32 %0, %1;" : "=r"(u) : "f"(x));
    return u;
}
__device__ __forceinline__ float to_tf32f(float x) { return __uint_as_float(tf32u(x)); }
__device__ __forceinline__ void mma8(float* d, const uint32_t* a, const uint32_t* b) {
    asm volatile(
        "mma.sync.aligned.m16n8k8.row.col.f32.tf32.tf32.f32 "
        "{%0,%1,%2,%3}, {%4,%5,%6,%7}, {%8,%9}, {%0,%1,%2,%3};"
        : "+f"(d[0]), "+f"(d[1]), "+f"(d[2]), "+f"(d[3])
        : "r"(a[0]), "r"(a[1]), "r"(a[2]), "r"(a[3]), "r"(b[0]), "r"(b[1]));
}
__device__ __forceinline__ uint32_t smem_u32(const void* p) {
    uint32_t a;
    asm("{ .reg .u64 t; cvta.to.shared.u64 t, %1; cvt.u32.u64 %0, t; }"
        : "=r"(a) : "l"(p));
    return a;
}
__device__ __forceinline__ void cp16(uint32_t dst, const void* src, int sz) {
    asm volatile("cp.async.cg.shared.global [%0], [%1], 16, %2;"
                 :: "r"(dst), "l"(src), "r"(sz));
}
#define CP_COMMIT() asm volatile("cp.async.commit_group;" ::: "memory")
#define CP_WAIT(n)  asm volatile("cp.async.wait_group %0;" :: "n"(n) : "memory")
__device__ __forceinline__ void ldsm4(uint32_t* r, uint32_t addr) {
    asm volatile("ldmatrix.sync.aligned.m8n8.x4.shared.b16 {%0,%1,%2,%3}, [%4];"
                 : "=r"(r[0]), "=r"(r[1]), "=r"(r[2]), "=r"(r[3]) : "r"(addr));
}

// A tile: 128 x 32 fp32, row stride 36 words (144 B)
// B tile:  32 x 64 fp32, row stride 72 words
#define A_STRIDE 36
#define B_STRIDE 72
#define A_ROWB   (A_STRIDE * 4)          // 144
#define A_BYTES  (128 * A_ROWB)          // 18432
#define B_BYTES  (BK * B_STRIDE * 4)     // 9216

// ------------------------------ init (counters only) ------------------------------
__global__ void zero_cnt_kernel() {
    if (threadIdx.x < NEXP) g_cnt[threadIdx.x] = 0;
}

// ------------------------------ router (+ zero own out rows) ------------------------------
__global__ __launch_bounds__(256) void router_kernel(
    const float* __restrict__ x, const float* __restrict__ Wr,
    const float* __restrict__ br, float* __restrict__ out)
{
    // zero the 8 output rows this block owns (8 * 768 floats = 1536 float4)
    {
        float4* ob = (float4*)(out + (size_t)blockIdx.x * 8 * HDIM);
#pragma unroll
        for (int i = 0; i < 6; i++)
            ob[threadIdx.x + i * 256] = make_float4(0.f, 0.f, 0.f, 0.f);
    }

    int warp = threadIdx.x >> 5;
    int lane = threadIdx.x & 31;
    int t = blockIdx.x * 8 + warp;
    if (t >= TTOK) return;

    const float4* xr = (const float4*)(x + (size_t)t * HDIM);
    float acc[NEXP];
#pragma unroll
    for (int e = 0; e < NEXP; e++) acc[e] = 0.f;

    for (int h4 = lane; h4 < HDIM / 4; h4 += 32) {
        float4 xv = xr[h4];
        const float* w = Wr + h4 * 4 * NEXP;
#pragma unroll
        for (int e = 0; e < NEXP; e++) {
            float s = fmaf(xv.x, w[e], 0.f);
            s = fmaf(xv.y, w[e + 8], s);
            s = fmaf(xv.z, w[e + 16], s);
            s = fmaf(xv.w, w[e + 24], s);
            acc[e] += s;
        }
    }
#pragma unroll
    for (int e = 0; e < NEXP; e++) {
#pragma unroll
        for (int o = 16; o > 0; o >>= 1)
            acc[e] += __shfl_xor_sync(0xffffffffu, acc[e], o);
    }
    if (lane == 0) {
#pragma unroll
        for (int e = 0; e < NEXP; e++) acc[e] += br[e];

        int i0 = 0; float v0 = acc[0];
#pragma unroll
        for (int e = 1; e < NEXP; e++)
            if (acc[e] > v0) { v0 = acc[e]; i0 = e; }
        int i1 = -1; float v1 = -INFINITY;
#pragma unroll
        for (int e = 0; e < NEXP; e++)
            if (e != i0 && acc[e] > v1) { v1 = acc[e]; i1 = e; }

        float s1 = expf(v1 - v0);
        float d  = 1.f + s1;
        g_w[t * 2 + 0] = 1.f / d;
        g_w[t * 2 + 1] = s1 / d;

        int p0 = atomicAdd(&g_cnt[i0], 1);
        g_list[i0 * MAXP + p0] = t * 2;
        int p1 = atomicAdd(&g_cnt[i1], 1);
        g_list[i1 * MAXP + p1] = t * 2 + 1;
    }
}

// =============== stage 1: tf32 mma gate/up GEMM + SwiGLU ===============
#define GU_STAGE (A_BYTES + 2 * B_BYTES)   // 36864

__global__ __launch_bounds__(256, 2) void gu_mma(
    const float* __restrict__ x, const float* __restrict__ Wgu,
    const float* __restrict__ bgu)
{
    int e   = blockIdx.z;
    int cnt = g_cnt[e];
    int m0  = blockIdx.y * 128;
    if (m0 >= cnt) return;
    int n0  = blockIdx.x * 64;

    extern __shared__ __align__(16) char dsm[];
    __shared__ int sSlot[128];

    int tid  = threadIdx.x;
    int wid  = tid >> 5, lane = tid & 31;
    int wM   = wid >> 1, wN = wid & 1;
    int gID  = lane >> 2, tg = lane & 3;

    for (int m = tid; m < 128; m += 256) {
        int idx = m0 + m;
        sSlot[m] = (idx < cnt) ? g_list[e * MAXP + idx] : -1;
    }
    __syncthreads();

    const float* Wg = Wgu + (size_t)e * HDIM * (2 * IDIM);
    uint32_t smb = smem_u32(dsm);
    // ldmatrix per-lane address offset within A tile
    uint32_t aOff = (uint32_t)(wM * 32 * A_ROWB + (lane & 15) * A_ROWB + (lane >> 4) * 16);

    const float* aSrc[4]; int aSz[4]; uint32_t aDst[4];
#pragma unroll
    for (int i = 0; i < 4; i++) {
        int idx = tid + i * 256;
        int m = idx >> 3, kq = idx & 7;
        int slot = sSlot[m];
        aSrc[i] = (slot >= 0) ? x + (size_t)(slot >> 1) * HDIM + kq * 4 : x;
        aSz[i]  = (slot >= 0) ? 16 : 0;
        aDst[i] = (uint32_t)(m * A_ROWB + kq * 16);
    }
    const float* bSrc[2]; uint32_t bDst[2];
#pragma unroll
    for (int i = 0; i < 2; i++) {
        int idx = tid + i * 256;
        int k = idx >> 4, n4 = idx & 15;
        bSrc[i] = Wg + (size_t)k * (2 * IDIM) + n0 + n4 * 4;
        bDst[i] = (uint32_t)(k * B_STRIDE + n4 * 4) * 4u;
    }

    float accG[2][4][4], accU[2][4][4];
#pragma unroll
    for (int mt = 0; mt < 2; mt++)
#pragma unroll
        for (int nt = 0; nt < 4; nt++)
#pragma unroll
            for (int q = 0; q < 4; q++) { accG[mt][nt][q] = 0.f; accU[mt][nt][q] = 0.f; }

#define GU_ISSUE(c) do {                                                       \
    uint32_t st = smb + (uint32_t)((c) % 3) * GU_STAGE;                        \
    int k0 = (c) * BK;                                                         \
    _Pragma("unroll")                                                          \
    for (int i = 0; i < 4; i++) cp16(st + aDst[i], aSrc[i] + k0, aSz[i]);      \
    _Pragma("unroll")                                                          \
    for (int i = 0; i < 2; i++) {                                              \
        const float* bp = bSrc[i] + (size_t)k0 * (2 * IDIM);                   \
        cp16(st + A_BYTES + bDst[i],           bp,        16);                 \
        cp16(st + A_BYTES + B_BYTES + bDst[i], bp + IDIM, 16);                 \
    } } while (0)

    GU_ISSUE(0); CP_COMMIT();
    GU_ISSUE(1); CP_COMMIT();

    for (int c = 0; c < NCH; c++) {
        CP_WAIT(1);
        __syncthreads();

        uint32_t stA = smb + (uint32_t)(c % 3) * GU_STAGE;
        const float* fBg = (const float*)(dsm + (c % 3) * GU_STAGE + A_BYTES);
        const float* fBu = (const float*)(dsm + (c % 3) * GU_STAGE + A_BYTES + B_BYTES);

#pragma unroll
        for (int k8 = 0; k8 < 4; k8++) {
            int k = k8 * 8;
            uint32_t a[2][4];
#pragma unroll
            for (int mt = 0; mt < 2; mt++) {
                ldsm4(a[mt], stA + aOff + (uint32_t)(mt * 16 * A_ROWB + k8 * 32));
#pragma unroll
                for (int q = 0; q < 4; q++)
                    a[mt][q] = tf32u(__uint_as_float(a[mt][q]));
            }
#pragma unroll
            for (int nt = 0; nt < 4; nt++) {
                int col = wN * 32 + nt * 8 + gID;
                uint32_t bg[2], bu[2];
                bg[0] = tf32u(fBg[(k + tg) * B_STRIDE + col]);
                bg[1] = tf32u(fBg[(k + tg + 4) * B_STRIDE + col]);
                bu[0] = tf32u(fBu[(k + tg) * B_STRIDE + col]);
                bu[1] = tf32u(fBu[(k + tg + 4) * B_STRIDE + col]);
#pragma unroll
                for (int mt = 0; mt < 2; mt++) {
                    mma8(accG[mt][nt], a[mt], bg);
                    mma8(accU[mt][nt], a[mt], bu);
                }
            }
        }
        __syncthreads();
        if (c + 2 < NCH) GU_ISSUE(c + 2);
        CP_COMMIT();
    }

    // ---- epilogue: bias + clamp + SwiGLU, tf32-rounded store to g_act ----
    const float* bge = bgu + (size_t)e * (2 * IDIM);
#pragma unroll
    for (int mt = 0; mt < 2; mt++) {
#pragma unroll
        for (int half = 0; half < 2; half++) {
            int row = wM * 32 + mt * 16 + half * 8 + gID;
            int slot = sSlot[row];
            if (slot < 0) continue;
            float* outp = g_act + (size_t)slot * IDIM;
#pragma unroll
            for (int nt = 0; nt < 4; nt++) {
                int col = n0 + wN * 32 + nt * 8 + 2 * tg;
                float g0 = accG[mt][nt][half * 2 + 0] + bge[col];
                float g1 = accG[mt][nt][half * 2 + 1] + bge[col + 1];
                float u0 = accU[mt][nt][half * 2 + 0] + bge[IDIM + col];
                float u1 = accU[mt][nt][half * 2 + 1] + bge[IDIM + col + 1];
                g0 = fminf(g0, LIMIT); g1 = fminf(g1, LIMIT);
                u0 = fmaxf(fminf(u0, LIMIT), -LIMIT);
                u1 = fmaxf(fminf(u1, LIMIT), -LIMIT);
                float s0 = 1.f / (1.f + expf(-ALPHA * g0));
                float s1 = 1.f / (1.f + expf(-ALPHA * g1));
                float2 o = make_float2(to_tf32f((u0 + 1.f) * (g0 * s0)),
                                       to_tf32f((u1 + 1.f) * (g1 * s1)));
                *(float2*)(outp + col) = o;
            }
        }
    }
}

// =============== stage 2: tf32 mma down GEMM + weighted atomic combine ===============
#define DN_STAGE (A_BYTES + B_BYTES)   // 27648

__global__ __launch_bounds__(256, 2) void down_mma(
    const float* __restrict__ Wd, const float* __restrict__ bd,
    float* __restrict__ out)
{
    int e   = blockIdx.z;
    int cnt = g_cnt[e];
    int m0  = blockIdx.y * 128;
    if (m0 >= cnt) return;
    int n0  = blockIdx.x * 64;

    extern __shared__ __align__(16) char dsm[];
    __shared__ int sSlot[128];

    int tid  = threadIdx.x;
    int wid  = tid >> 5, lane = tid & 31;
    int wM   = wid >> 1, wN = wid & 1;
    int gID  = lane >> 2, tg = lane & 3;

    for (int m = tid; m < 128; m += 256) {
        int idx = m0 + m;
        sSlot[m] = (idx < cnt) ? g_list[e * MAXP + idx] : -1;
    }
    __syncthreads();

    const float* We = Wd + (size_t)e * IDIM * HDIM;
    uint32_t smb = smem_u32(dsm);
    uint32_t aOff = (uint32_t)(wM * 32 * A_ROWB + (lane & 15) * A_ROWB + (lane >> 4) * 16);

    const float* aSrc[4]; int aSz[4]; uint32_t aDst[4];
#pragma unroll
    for (int i = 0; i < 4; i++) {
        int idx = tid + i * 256;
        int m = idx >> 3, kq = idx & 7;
        int slot = sSlot[m];
        aSrc[i] = (slot >= 0) ? g_act + (size_t)slot * IDIM + kq * 4 : g_act;
        aSz[i]  = (slot >= 0) ? 16 : 0;
        aDst[i] = (uint32_t)(m * A_ROWB + kq * 16);
    }
    const float* bSrc[2]; uint32_t bDst[2];
#pragma unroll
    for (int i = 0; i < 2; i++) {
        int idx = tid + i * 256;
        int k = idx >> 4, n4 = idx & 15;
        bSrc[i] = We + (size_t)k * HDIM + n0 + n4 * 4;
        bDst[i] = (uint32_t)(k * B_STRIDE + n4 * 4) * 4u;
    }

    float acc[2][4][4];
#pragma unroll
    for (int mt = 0; mt < 2; mt++)
#pragma unroll
        for (int nt = 0; nt < 4; nt++)
#pragma unroll
            for (int q = 0; q < 4; q++) acc[mt][nt][q] = 0.f;

#define DN_ISSUE(c) do {                                                       \
    uint32_t st = smb + (uint32_t)((c) % 3) * DN_STAGE;                        \
    int k0 = (c) * BK;                                                         \
    _Pragma("unroll")                                                          \
    for (int i = 0; i < 4; i++) cp16(st + aDst[i], aSrc[i] + k0, aSz[i]);      \
    _Pragma("unroll")                                                          \
    for (int i = 0; i < 2; i++)                                                \
        cp16(st + A_BYTES + bDst[i], bSrc[i] + (size_t)k0 * HDIM, 16);         \
    } while (0)

    DN_ISSUE(0); CP_COMMIT();
    DN_ISSUE(1); CP_COMMIT();

    for (int c = 0; c < NCH; c++) {
        CP_WAIT(1);
        __syncthreads();

        uint32_t stA = smb + (uint32_t)(c % 3) * DN_STAGE;
        const float* fB = (const float*)(dsm + (c % 3) * DN_STAGE + A_BYTES);

#pragma unroll
        for (int k8 = 0; k8 < 4; k8++) {
            int k = k8 * 8;
            uint32_t a[2][4];
#pragma unroll
            for (int mt = 0; mt < 2; mt++)
                ldsm4(a[mt], stA + aOff + (uint32_t)(mt * 16 * A_ROWB + k8 * 32));
#pragma unroll
            for (int nt = 0; nt < 4; nt++) {
                int col = wN * 32 + nt * 8 + gID;
                uint32_t b[2];
                b[0] = tf32u(fB[(k + tg) * B_STRIDE + col]);
                b[1] = tf32u(fB[(k + tg + 4) * B_STRIDE + col]);
#pragma unroll
                for (int mt = 0; mt < 2; mt++)
                    mma8(acc[mt][nt], a[mt], b);
            }
        }
        __syncthreads();
        if (c + 2 < NCH) DN_ISSUE(c + 2);
        CP_COMMIT();
    }

    // ---- epilogue: weighted atomic accumulate into out ----
    const float* bde = bd + (size_t)e * HDIM;
#pragma unroll
    for (int mt = 0; mt < 2; mt++) {
#pragma unroll
        for (int half = 0; half < 2; half++) {
            int row = wM * 32 + mt * 16 + half * 8 + gID;
            int slot = sSlot[row];
            if (slot < 0) continue;
            float w = g_w[slot];
            float* outp = out + (size_t)(slot >> 1) * HDIM;
#pragma unroll
            for (int nt = 0; nt < 4; nt++) {
                int col = n0 + wN * 32 + nt * 8 + 2 * tg;
                atomicAdd(outp + col,     w * (acc[mt][nt][half * 2 + 0] + bde[col]));
                atomicAdd(outp + col + 1, w * (acc[mt][nt][half * 2 + 1] + bde[col + 1]));
            }
        }
    }
}

// ------------------------------ launch ------------------------------
extern "C" void kernel_launch(void* const* d_in, const int* in_sizes, int n_in,
                              void* d_out, int out_size)
{
    const float* x   = (const float*)d_in[0];
    const float* Wr  = (const float*)d_in[1];
    const float* br  = (const float*)d_in[2];
    const float* Wgu = (const float*)d_in[3];
    const float* bgu = (const float*)d_in[4];
    const float* Wd  = (const float*)d_in[5];
    const float* bd  = (const float*)d_in[6];
    float* out = (float*)d_out;

    const int GU_SMEM = 3 * GU_STAGE;   // 110592
    const int DN_SMEM = 3 * DN_STAGE;   // 82944
    cudaFuncSetAttribute(gu_mma,   cudaFuncAttributeMaxDynamicSharedMemorySize, GU_SMEM);
    cudaFuncSetAttribute(down_mma, cudaFuncAttributeMaxDynamicSharedMemorySize, DN_SMEM);

    zero_cnt_kernel<<<1, 32>>>();
    router_kernel<<<TTOK / 8, 256>>>(x, Wr, br, out);

    dim3 ggrid(IDIM / 64, MAXP / 128, NEXP);   // (12, 32, 8)
    gu_mma<<<ggrid, 256, GU_SMEM>>>(x, Wgu, bgu);

    dim3 dgrid(HDIM / 64, MAXP / 128, NEXP);   // (12, 32, 8)
    down_mma<<<dgrid, 256, DN_SMEM>>>(Wd, bd, out);
}

// round 8
// speedup vs baseline: 1.0551x; 1.0034x over previous
#include <cuda_runtime.h>
#include <math.h>
#include <stdint.h>

#define TTOK   2048
#define HDIM   768
#define NEXP   8
#define IDIM   768
#define MAXP   (TTOK*2)
#define ALPHA  1.702f
#define LIMIT  7.0f
#define BK     32
#define NCH    (HDIM / BK)   // 24

// -------- scratch --------
__device__ int   g_cnt[NEXP];
__device__ int   g_list[NEXP * MAXP];
__device__ float g_w[TTOK * 2];
__device__ float g_act[(size_t)TTOK * 2 * IDIM];   // stored tf32-rounded

// ------------------------- helpers -------------------------
__device__ __forceinline__ uint32_t tf32u(float x) {
    uint32_t u;
    asm("cvt.rna.tf32.f32 %0, %1;" : "=r"(u) : "f"(x));
    return u;
}
__device__ __forceinline__ float to_tf32f(float x) { return __uint_as_float(tf32u(x)); }
__device__ __forceinline__ void mma8(float* d, const uint32_t* a, const uint32_t* b) {
    asm volatile(
        "mma.sync.aligned.m16n8k8.row.col.f32.tf32.tf32.f32 "
        "{%0,%1,%2,%3}, {%4,%5,%6,%7}, {%8,%9}, {%0,%1,%2,%3};"
        : "+f"(d[0]), "+f"(d[1]), "+f"(d[2]), "+f"(d[3])
        : "r"(a[0]), "r"(a[1]), "r"(a[2]), "r"(a[3]), "r"(b[0]), "r"(b[1]));
}
__device__ __forceinline__ uint32_t smem_u32(const void* p) {
    uint32_t a;
    asm("{ .reg .u64 t; cvta.to.shared.u64 t, %1; cvt.u32.u64 %0, t; }"
        : "=r"(a) : "l"(p));
    return a;
}
__device__ __forceinline__ void cp16(uint32_t dst, const void* src, int sz) {
    asm volatile("cp.async.cg.shared.global [%0], [%1], 16, %2;"
                 :: "r"(dst), "l"(src), "r"(sz));
}
#define CP_COMMIT() asm volatile("cp.async.commit_group;" ::: "memory")
#define CP_WAIT(n)  asm volatile("cp.async.wait_group %0;" :: "n"(n) : "memory")
__device__ __forceinline__ void ldsm4(uint32_t* r, uint32_t addr) {
    asm volatile("ldmatrix.sync.aligned.m8n8.x4.shared.b16 {%0,%1,%2,%3}, [%4];"
                 : "=r"(r[0]), "=r"(r[1]), "=r"(r[2]), "=r"(r[3]) : "r"(addr));
}

// A tile: 128 x 32 fp32, row stride 36 words (144 B)
// B tile:  32 x 64 fp32, row stride 72 words
#define A_STRIDE 36
#define B_STRIDE 72
#define A_ROWB   (A_STRIDE * 4)          // 144
#define A_BYTES  (128 * A_ROWB)          // 18432
#define B_BYTES  (BK * B_STRIDE * 4)     // 9216

// ------------------------------ init (counters only) ------------------------------
__global__ void zero_cnt_kernel() {
    if (threadIdx.x < NEXP) g_cnt[threadIdx.x] = 0;
}

// ------------------------------ router (+ zero own out rows) ------------------------------
__global__ __launch_bounds__(256) void router_kernel(
    const float* __restrict__ x, const float* __restrict__ Wr,
    const float* __restrict__ br, float* __restrict__ out)
{
    // zero the 8 output rows this block owns (8 * 768 floats = 1536 float4)
    {
        float4* ob = (float4*)(out + (size_t)blockIdx.x * 8 * HDIM);
#pragma unroll
        for (int i = 0; i < 6; i++)
            ob[threadIdx.x + i * 256] = make_float4(0.f, 0.f, 0.f, 0.f);
    }

    int warp = threadIdx.x >> 5;
    int lane = threadIdx.x & 31;
    int t = blockIdx.x * 8 + warp;
    if (t >= TTOK) return;

    const float4* xr = (const float4*)(x + (size_t)t * HDIM);
    float acc[NEXP];
#pragma unroll
    for (int e = 0; e < NEXP; e++) acc[e] = 0.f;

    for (int h4 = lane; h4 < HDIM / 4; h4 += 32) {
        float4 xv = xr[h4];
        const float* w = Wr + h4 * 4 * NEXP;
#pragma unroll
        for (int e = 0; e < NEXP; e++) {
            float s = fmaf(xv.x, w[e], 0.f);
            s = fmaf(xv.y, w[e + 8], s);
            s = fmaf(xv.z, w[e + 16], s);
            s = fmaf(xv.w, w[e + 24], s);
            acc[e] += s;
        }
    }
#pragma unroll
    for (int e = 0; e < NEXP; e++) {
#pragma unroll
        for (int o = 16; o > 0; o >>= 1)
            acc[e] += __shfl_xor_sync(0xffffffffu, acc[e], o);
    }
    if (lane == 0) {
#pragma unroll
        for (int e = 0; e < NEXP; e++) acc[e] += br[e];

        int i0 = 0; float v0 = acc[0];
#pragma unroll
        for (int e = 1; e < NEXP; e++)
            if (acc[e] > v0) { v0 = acc[e]; i0 = e; }
        int i1 = -1; float v1 = -INFINITY;
#pragma unroll
        for (int e = 0; e < NEXP; e++)
            if (e != i0 && acc[e] > v1) { v1 = acc[e]; i1 = e; }

        float s1 = expf(v1 - v0);
        float d  = 1.f + s1;
        g_w[t * 2 + 0] = 1.f / d;
        g_w[t * 2 + 1] = s1 / d;

        int p0 = atomicAdd(&g_cnt[i0], 1);
        g_list[i0 * MAXP + p0] = t * 2;
        int p1 = atomicAdd(&g_cnt[i1], 1);
        g_list[i1 * MAXP + p1] = t * 2 + 1;
    }
}

// =============== stage 1: tf32 mma gate/up GEMM + SwiGLU (R4 structure) ===============
#define GU_STAGE (A_BYTES + 2 * B_BYTES)   // 36864

__global__ __launch_bounds__(256, 2) void gu_mma(
    const float* __restrict__ x, const float* __restrict__ Wgu,
    const float* __restrict__ bgu)
{
    int e   = blockIdx.z;
    int cnt = g_cnt[e];
    int m0  = blockIdx.y * 128;
    if (m0 >= cnt) return;
    int n0  = blockIdx.x * 64;

    extern __shared__ __align__(16) char dsm[];
    __shared__ int sSlot[128];

    int tid  = threadIdx.x;
    int wid  = tid >> 5, lane = tid & 31;
    int wM   = wid >> 1, wN = wid & 1;
    int gID  = lane >> 2, tg = lane & 3;

    for (int m = tid; m < 128; m += 256) {
        int idx = m0 + m;
        sSlot[m] = (idx < cnt) ? g_list[e * MAXP + idx] : -1;
    }
    __syncthreads();

    const float* Wg = Wgu + (size_t)e * HDIM * (2 * IDIM);
    uint32_t smb = smem_u32(dsm);

    const float* aSrc[4]; int aSz[4]; uint32_t aDst[4];
#pragma unroll
    for (int i = 0; i < 4; i++) {
        int idx = tid + i * 256;
        int m = idx >> 3, kq = idx & 7;
        int slot = sSlot[m];
        aSrc[i] = (slot >= 0) ? x + (size_t)(slot >> 1) * HDIM + kq * 4 : x;
        aSz[i]  = (slot >= 0) ? 16 : 0;
        aDst[i] = (uint32_t)(m * A_ROWB + kq * 16);
    }
    const float* bSrc[2]; uint32_t bDst[2];
#pragma unroll
    for (int i = 0; i < 2; i++) {
        int idx = tid + i * 256;
        int k = idx >> 4, n4 = idx & 15;
        bSrc[i] = Wg + (size_t)k * (2 * IDIM) + n0 + n4 * 4;
        bDst[i] = (uint32_t)(k * B_STRIDE + n4 * 4) * 4u;
    }

    float accG[2][4][4], accU[2][4][4];
#pragma unroll
    for (int mt = 0; mt < 2; mt++)
#pragma unroll
        for (int nt = 0; nt < 4; nt++)
#pragma unroll
            for (int q = 0; q < 4; q++) { accG[mt][nt][q] = 0.f; accU[mt][nt][q] = 0.f; }

#define GU_ISSUE(c) do {                                                       \
    uint32_t st = smb + (uint32_t)((c) % 3) * GU_STAGE;                        \
    int k0 = (c) * BK;                                                         \
    _Pragma("unroll")                                                          \
    for (int i = 0; i < 4; i++) cp16(st + aDst[i], aSrc[i] + k0, aSz[i]);      \
    _Pragma("unroll")                                                          \
    for (int i = 0; i < 2; i++) {                                              \
        const float* bp = bSrc[i] + (size_t)k0 * (2 * IDIM);                   \
        cp16(st + A_BYTES + bDst[i],           bp,        16);                 \
        cp16(st + A_BYTES + B_BYTES + bDst[i], bp + IDIM, 16);                 \
    } } while (0)

    GU_ISSUE(0); CP_COMMIT();
    GU_ISSUE(1); CP_COMMIT();

    for (int c = 0; c < NCH; c++) {
        CP_WAIT(1);
        __syncthreads();

        const float* fA  = (const float*)(dsm + (c % 3) * GU_STAGE);
        const float* fBg = (const float*)(dsm + (c % 3) * GU_STAGE + A_BYTES);
        const float* fBu = (const float*)(dsm + (c % 3) * GU_STAGE + A_BYTES + B_BYTES);

#pragma unroll
        for (int k8 = 0; k8 < 4; k8++) {
            int k = k8 * 8;
            uint32_t a[2][4];
#pragma unroll
            for (int mt = 0; mt < 2; mt++) {
                int r0 = wM * 32 + mt * 16 + gID;
                a[mt][0] = tf32u(fA[r0 * A_STRIDE + k + tg]);
                a[mt][1] = tf32u(fA[(r0 + 8) * A_STRIDE + k + tg]);
                a[mt][2] = tf32u(fA[r0 * A_STRIDE + k + tg + 4]);
                a[mt][3] = tf32u(fA[(r0 + 8) * A_STRIDE + k + tg + 4]);
            }
#pragma unroll
            for (int nt = 0; nt < 4; nt++) {
                int col = wN * 32 + nt * 8 + gID;
                uint32_t bg[2], bu[2];
                bg[0] = tf32u(fBg[(k + tg) * B_STRIDE + col]);
                bg[1] = tf32u(fBg[(k + tg + 4) * B_STRIDE + col]);
                bu[0] = tf32u(fBu[(k + tg) * B_STRIDE + col]);
                bu[1] = tf32u(fBu[(k + tg + 4) * B_STRIDE + col]);
#pragma unroll
                for (int mt = 0; mt < 2; mt++) {
                    mma8(accG[mt][nt], a[mt], bg);
                    mma8(accU[mt][nt], a[mt], bu);
                }
            }
        }
        __syncthreads();
        if (c + 2 < NCH) GU_ISSUE(c + 2);
        CP_COMMIT();
    }

    // ---- epilogue: bias + clamp + SwiGLU, tf32-rounded store to g_act ----
    const float* bge = bgu + (size_t)e * (2 * IDIM);
#pragma unroll
    for (int mt = 0; mt < 2; mt++) {
#pragma unroll
        for (int half = 0; half < 2; half++) {
            int row = wM * 32 + mt * 16 + half * 8 + gID;
            int slot = sSlot[row];
            if (slot < 0) continue;
            float* outp = g_act + (size_t)slot * IDIM;
#pragma unroll
            for (int nt = 0; nt < 4; nt++) {
                int col = n0 + wN * 32 + nt * 8 + 2 * tg;
                float g0 = accG[mt][nt][half * 2 + 0] + bge[col];
                float g1 = accG[mt][nt][half * 2 + 1] + bge[col + 1];
                float u0 = accU[mt][nt][half * 2 + 0] + bge[IDIM + col];
                float u1 = accU[mt][nt][half * 2 + 1] + bge[IDIM + col + 1];
                g0 = fminf(g0, LIMIT); g1 = fminf(g1, LIMIT);
                u0 = fmaxf(fminf(u0, LIMIT), -LIMIT);
                u1 = fmaxf(fminf(u1, LIMIT), -LIMIT);
                float s0 = 1.f / (1.f + expf(-ALPHA * g0));
                float s1 = 1.f / (1.f + expf(-ALPHA * g1));
                float2 o = make_float2(to_tf32f((u0 + 1.f) * (g0 * s0)),
                                       to_tf32f((u1 + 1.f) * (g1 * s1)));
                *(float2*)(outp + col) = o;
            }
        }
    }
}

// =============== stage 2: tf32 mma down GEMM (LDSM A) + weighted atomic combine ===============
#define DN_STAGE (A_BYTES + B_BYTES)   // 27648

__global__ __launch_bounds__(256, 2) void down_mma(
    const float* __restrict__ Wd, const float* __restrict__ bd,
    float* __restrict__ out)
{
    int e   = blockIdx.z;
    int cnt = g_cnt[e];
    int m0  = blockIdx.y * 128;
    if (m0 >= cnt) return;
    int n0  = blockIdx.x * 64;

    extern __shared__ __align__(16) char dsm[];
    __shared__ int sSlot[128];

    int tid  = threadIdx.x;
    int wid  = tid >> 5, lane = tid & 31;
    int wM   = wid >> 1, wN = wid & 1;
    int gID  = lane >> 2, tg = lane & 3;

    for (int m = tid; m < 128; m += 256) {
        int idx = m0 + m;
        sSlot[m] = (idx < cnt) ? g_list[e * MAXP + idx] : -1;
    }
    __syncthreads();

    const float* We = Wd + (size_t)e * IDIM * HDIM;
    uint32_t smb = smem_u32(dsm);
    uint32_t aOff = (uint32_t)(wM * 32 * A_ROWB + (lane & 15) * A_ROWB + (lane >> 4) * 16);

    const float* aSrc[4]; int aSz[4]; uint32_t aDst[4];
#pragma unroll
    for (int i = 0; i < 4; i++) {
        int idx = tid + i * 256;
        int m = idx >> 3, kq = idx & 7;
        int slot = sSlot[m];
        aSrc[i] = (slot >= 0) ? g_act + (size_t)slot * IDIM + kq * 4 : g_act;
        aSz[i]  = (slot >= 0) ? 16 : 0;
        aDst[i] = (uint32_t)(m * A_ROWB + kq * 16);
    }
    const float* bSrc[2]; uint32_t bDst[2];
#pragma unroll
    for (int i = 0; i < 2; i++) {
        int idx = tid + i * 256;
        int k = idx >> 4, n4 = idx & 15;
        bSrc[i] = We + (size_t)k * HDIM + n0 + n4 * 4;
        bDst[i] = (uint32_t)(k * B_STRIDE + n4 * 4) * 4u;
    }

    float acc[2][4][4];
#pragma unroll
    for (int mt = 0; mt < 2; mt++)
#pragma unroll
        for (int nt = 0; nt < 4; nt++)
#pragma unroll
            for (int q = 0; q < 4; q++) acc[mt][nt][q] = 0.f;

#define DN_ISSUE(c) do {                                                       \
    uint32_t st = smb + (uint32_t)((c) % 3) * DN_STAGE;                        \
    int k0 = (c) * BK;                                                         \
    _Pragma("unroll")                                                          \
    for (int i = 0; i < 4; i++) cp16(st + aDst[i], aSrc[i] + k0, aSz[i]);      \
    _Pragma("unroll")                                                          \
    for (int i = 0; i < 2; i++)                                                \
        cp16(st + A_BYTES + bDst[i], bSrc[i] + (size_t)k0 * HDIM, 16);         \
    } while (0)

    DN_ISSUE(0); CP_COMMIT();
    DN_ISSUE(1); CP_COMMIT();

    for (int c = 0; c < NCH; c++) {
        CP_WAIT(1);
        __syncthreads();

        uint32_t stA = smb + (uint32_t)(c % 3) * DN_STAGE;
        const float* fB = (const float*)(dsm + (c % 3) * DN_STAGE + A_BYTES);

#pragma unroll
        for (int k8 = 0; k8 < 4; k8++) {
            int k = k8 * 8;
            uint32_t a[2][4];
#pragma unroll
            for (int mt = 0; mt < 2; mt++)
                ldsm4(a[mt], stA + aOff + (uint32_t)(mt * 16 * A_ROWB + k8 * 32));
#pragma unroll
            for (int nt = 0; nt < 4; nt++) {
                int col = wN * 32 + nt * 8 + gID;
                uint32_t b[2];
                b[0] = tf32u(fB[(k + tg) * B_STRIDE + col]);
                b[1] = tf32u(fB[(k + tg + 4) * B_STRIDE + col]);
#pragma unroll
                for (int mt = 0; mt < 2; mt++)
                    mma8(acc[mt][nt], a[mt], b);
            }
        }
        __syncthreads();
        if (c + 2 < NCH) DN_ISSUE(c + 2);
        CP_COMMIT();
    }

    // ---- epilogue: weighted atomic accumulate into out ----
    const float* bde = bd + (size_t)e * HDIM;
#pragma unroll
    for (int mt = 0; mt < 2; mt++) {
#pragma unroll
        for (int half = 0; half < 2; half++) {
            int row = wM * 32 + mt * 16 + half * 8 + gID;
            int slot = sSlot[row];
            if (slot < 0) continue;
            float w = g_w[slot];
            float* outp = out + (size_t)(slot >> 1) * HDIM;
#pragma unroll
            for (int nt = 0; nt < 4; nt++) {
                int col = n0 + wN * 32 + nt * 8 + 2 * tg;
                atomicAdd(outp + col,     w * (acc[mt][nt][half * 2 + 0] + bde[col]));
                atomicAdd(outp + col + 1, w * (acc[mt][nt][half * 2 + 1] + bde[col + 1]));
            }
        }
    }
}

// ------------------------------ launch ------------------------------
extern "C" void kernel_launch(void* const* d_in, const int* in_sizes, int n_in,
                              void* d_out, int out_size)
{
    const float* x   = (const float*)d_in[0];
    const float* Wr  = (const float*)d_in[1];
    const float* br  = (const float*)d_in[2];
    const float* Wgu = (const float*)d_in[3];
    const float* bgu = (const float*)d_in[4];
    const float* Wd  = (const float*)d_in[5];
    const float* bd  = (const float*)d_in[6];
    float* out = (float*)d_out;

    const int GU_SMEM = 3 * GU_STAGE;   // 110592
    const int DN_SMEM = 3 * DN_STAGE;   // 82944
    cudaFuncSetAttribute(gu_mma,   cudaFuncAttributeMaxDynamicSharedMemorySize, GU_SMEM);
    cudaFuncSetAttribute(down_mma, cudaFuncAttributeMaxDynamicSharedMemorySize, DN_SMEM);

    zero_cnt_kernel<<<1, 32>>>();
    router_kernel<<<TTOK / 8, 256>>>(x, Wr, br, out);

    dim3 ggrid(IDIM / 64, MAXP / 128, NEXP);   // (12, 32, 8)
    gu_mma<<<ggrid, 256, GU_SMEM>>>(x, Wgu, bgu);

    dim3 dgrid(HDIM / 64, MAXP / 128, NEXP);   // (12, 32, 8)
    down_mma<<<dgrid, 256, DN_SMEM>>>(Wd, bd, out);
}